// round 6
// baseline (speedup 1.0000x reference)
#include <cuda_runtime.h>
#include <cuda_fp16.h>
#include <cuda_bf16.h>
#include <stdint.h>

#define N_NODES 100000
#define N_EDGES 3200000
#define DIM 128
#define DIM4 32
#define SCAN_NB 98   // ceil(100000/1024)

// ---------------- scratch (device globals) ----------------
__device__ int   g_is64;
__device__ float g_deg[N_NODES];
__device__ float g_dinv[N_NODES];
__device__ int   g_hist[N_NODES];
__device__ int   g_offs[N_NODES];
__device__ int   g_cursor[N_NODES];
__device__ int2  g_edge[N_EDGES];                  // (src row, coef bits)
__device__ int   g_psum[256];
__device__ int   g_poff[256];
__device__ uint4 g_h16a[(size_t)N_NODES * 16];     // layer-1 fp16 messages
__device__ uint4 g_h16b[(size_t)N_NODES * 16];     // layer-2 fp16 messages

// ---------------- edge index readers (dtype-agnostic) ----------------
__device__ __forceinline__ int read_row(const void* ei, int E, int i) {
    if (g_is64) return (int)((const long long*)ei)[i];
    return ((const int*)ei)[i];
}
__device__ __forceinline__ int read_col(const void* ei, int E, int i) {
    if (g_is64) return (int)((const long long*)ei)[(size_t)E + i];
    return ((const int*)ei)[(size_t)E + i];
}

// ---------------- f32x2 helpers ----------------
__device__ __forceinline__ unsigned long long dup2(float v) {
    unsigned long long d;
    asm("mov.b64 %0, {%1, %1};" : "=l"(d) : "f"(v));
    return d;
}
__device__ __forceinline__ unsigned long long fma2(unsigned long long a,
                                                   unsigned long long b,
                                                   unsigned long long c) {
    unsigned long long d;
    asm("fma.rn.f32x2 %0, %1, %2, %3;" : "=l"(d) : "l"(a), "l"(b), "l"(c));
    return d;
}
__device__ __forceinline__ float2 unpack2(unsigned long long v) {
    float2 f;
    f.x = __uint_as_float((unsigned)(v & 0xffffffffull));
    f.y = __uint_as_float((unsigned)(v >> 32));
    return f;
}

// ---------------- init: deg=1, hist=0; block 0 detects dtype ----------------
__global__ void init_kernel(const int* ei_words, int n) {
    int i = blockIdx.x * blockDim.x + threadIdx.x;
    if (i < n) { g_deg[i] = 1.0f; g_hist[i] = 0; }
    if (blockIdx.x == 0 && threadIdx.x == 0) {
        int is64 = 1;
        #pragma unroll 1
        for (int k = 0; k < 64; k++)
            if (ei_words[2 * k + 1] != 0) { is64 = 0; break; }
        g_is64 = is64;
    }
}

// ================ fused1: blocks [0,nbg) gemm1, blocks [nbg,..) deg_hist ================
// gemm core: quarter-staged W (16KB smem); each warp does 4 rows, lane -> cols [4l,4l+3]
__global__ __launch_bounds__(256) void fused1_kernel(
        const float* __restrict__ x, const float* __restrict__ W1,
        const void* __restrict__ ei, const float* __restrict__ ew,
        int E, int n, int nbg) {
    __shared__ ulonglong2 Ws[32 * DIM4];  // 32 k-rows x 128 cols = 16KB

    if (blockIdx.x >= nbg) {
        // ---- deg_hist part ----
        int i = (blockIdx.x - nbg) * 256 + threadIdx.x;
        if (i < E) {
            int c = read_col(ei, E, i);
            if ((unsigned)c < (unsigned)n) {
                atomicAdd(&g_deg[c], ew[i]);
                atomicAdd(&g_hist[c], 1);
            }
        }
        return;
    }

    // ---- gemm1 part: g_h16a = fp16(x @ W1) ----
    const float4* X4 = (const float4*)x;
    int lane = threadIdx.x & 31, wid = threadIdx.x >> 5;
    int r0 = blockIdx.x * 32 + wid * 4;

    unsigned long long a01[4], a23[4];
    #pragma unroll
    for (int ri = 0; ri < 4; ri++) { a01[ri] = 0ull; a23[ri] = 0ull; }

    #pragma unroll 1
    for (int q = 0; q < 4; q++) {
        const ulonglong2* Wq = (const ulonglong2*)(W1 + (size_t)q * 32 * DIM);
        for (int idx = threadIdx.x; idx < 32 * DIM4; idx += 256)
            Ws[idx] = Wq[idx];
        __syncthreads();
        if (r0 < n) {
            #pragma unroll
            for (int kk = 0; kk < 8; kk++) {
                ulonglong2 w0 = Ws[(4 * kk + 0) * DIM4 + lane];
                ulonglong2 w1 = Ws[(4 * kk + 1) * DIM4 + lane];
                ulonglong2 w2 = Ws[(4 * kk + 2) * DIM4 + lane];
                ulonglong2 w3 = Ws[(4 * kk + 3) * DIM4 + lane];
                #pragma unroll
                for (int ri = 0; ri < 4; ri++) {
                    int r = r0 + ri;
                    if (r < n) {
                        float4 xv = X4[(size_t)r * DIM4 + q * 8 + kk];
                        unsigned long long x0 = dup2(xv.x), x1 = dup2(xv.y);
                        unsigned long long x2 = dup2(xv.z), x3 = dup2(xv.w);
                        a01[ri] = fma2(x0, w0.x, a01[ri]); a23[ri] = fma2(x0, w0.y, a23[ri]);
                        a01[ri] = fma2(x1, w1.x, a01[ri]); a23[ri] = fma2(x1, w1.y, a23[ri]);
                        a01[ri] = fma2(x2, w2.x, a01[ri]); a23[ri] = fma2(x2, w2.y, a23[ri]);
                        a01[ri] = fma2(x3, w3.x, a01[ri]); a23[ri] = fma2(x3, w3.y, a23[ri]);
                    }
                }
            }
        }
        __syncthreads();
    }

    uint2* H2 = (uint2*)g_h16a;
    #pragma unroll
    for (int ri = 0; ri < 4; ri++) {
        int r = r0 + ri;
        if (r < n) {
            float2 c01 = unpack2(a01[ri]);
            float2 c23 = unpack2(a23[ri]);
            __half2 p0 = __floats2half2_rn(c01.x, c01.y);
            __half2 p1 = __floats2half2_rn(c23.x, c23.y);
            uint2 o; o.x = *(unsigned*)&p0; o.y = *(unsigned*)&p1;
            H2[(size_t)r * 32 + lane] = o;
        }
    }
}

// ---------------- scan phase 1: per-block partial sums of hist; fused dinv ----------------
__global__ __launch_bounds__(256) void scan_phase1(int n) {
    __shared__ int ws[8];
    int b = blockIdx.x, tid = threadIdx.x;
    int base = b * 1024;
    int s = 0;
    #pragma unroll
    for (int j = 0; j < 4; j++) {
        int i = base + j * 256 + tid;
        if (i < n) {
            s += g_hist[i];
            float d = g_deg[i];
            g_dinv[i] = (d > 0.0f) ? rsqrtf(d) : 0.0f;
        }
    }
    #pragma unroll
    for (int o = 16; o; o >>= 1) s += __shfl_xor_sync(0xffffffffu, s, o);
    if ((tid & 31) == 0) ws[tid >> 5] = s;
    __syncthreads();
    if (tid == 0) {
        int t = 0;
        #pragma unroll
        for (int j = 0; j < 8; j++) t += ws[j];
        g_psum[b] = t;
    }
}

// ---------------- scan phase 2: single warp scans the partials ----------------
__global__ void scan_phase2() {
    int lane = threadIdx.x;
    int carry = 0;
    #pragma unroll
    for (int base = 0; base < SCAN_NB; base += 32) {
        int i = base + lane;
        int v = (i < SCAN_NB) ? g_psum[i] : 0;
        int incl = v;
        #pragma unroll
        for (int s = 1; s < 32; s <<= 1) {
            int t = __shfl_up_sync(0xffffffffu, incl, s);
            if (lane >= s) incl += t;
        }
        if (i < SCAN_NB) g_poff[i] = carry + incl - v;
        carry += __shfl_sync(0xffffffffu, incl, 31);
    }
}

// ---------------- scan phase 3: local exclusive scan + block offset ----------------
__global__ __launch_bounds__(256) void scan_phase3(int n) {
    __shared__ int wsum[8];
    int b = blockIdx.x, tid = threadIdx.x, lane = tid & 31, wid = tid >> 5;
    int base = b * 1024 + tid * 4;
    int v0 = 0, v1 = 0, v2 = 0, v3 = 0;
    if (base + 3 < n) {
        int4 v = *(const int4*)&g_hist[base];
        v0 = v.x; v1 = v.y; v2 = v.z; v3 = v.w;
    } else {
        if (base + 0 < n) v0 = g_hist[base + 0];
        if (base + 1 < n) v1 = g_hist[base + 1];
        if (base + 2 < n) v2 = g_hist[base + 2];
        if (base + 3 < n) v3 = g_hist[base + 3];
    }
    int t = v0 + v1 + v2 + v3;
    int incl = t;
    #pragma unroll
    for (int s = 1; s < 32; s <<= 1) {
        int u = __shfl_up_sync(0xffffffffu, incl, s);
        if (lane >= s) incl += u;
    }
    if (lane == 31) wsum[wid] = incl;
    __syncthreads();
    if (tid == 0) {
        int run = 0;
        #pragma unroll
        for (int j = 0; j < 8; j++) { int u = wsum[j]; wsum[j] = run; run += u; }
    }
    __syncthreads();
    int excl = g_poff[b] + wsum[wid] + incl - t;
    if (base + 0 < n) { g_offs[base + 0] = excl; g_cursor[base + 0] = excl; } excl += v0;
    if (base + 1 < n) { g_offs[base + 1] = excl; g_cursor[base + 1] = excl; } excl += v1;
    if (base + 2 < n) { g_offs[base + 2] = excl; g_cursor[base + 2] = excl; } excl += v2;
    if (base + 3 < n) { g_offs[base + 3] = excl; g_cursor[base + 3] = excl; }
}

// ---------------- scatter edges into CSR bins ----------------
__global__ void scatter_kernel(const void* __restrict__ ei,
                               const float* __restrict__ ew, int E, int n) {
    int i = blockIdx.x * blockDim.x + threadIdx.x;
    if (i < E) {
        int r = read_row(ei, E, i);
        int c = read_col(ei, E, i);
        if ((unsigned)r >= (unsigned)n || (unsigned)c >= (unsigned)n) return;
        int pos = atomicAdd(&g_cursor[c], 1);
        if ((unsigned)pos < (unsigned)E)
            g_edge[pos] = make_int2(r, __float_as_int(ew[i] * g_dinv[r]));
    }
}

// ---------------- agg core (device): aggregate one node from src buffer ----------------
// returns this lane-half's float4 result (cols (li*2+hf)*4 .. +3), relu optional
__device__ __forceinline__ float4 agg_node(const uint4* __restrict__ src,
                                           const float* __restrict__ bias,
                                           int node, int hf, int li, int do_relu) {
    int off = g_offs[node];
    int end = off + g_hist[node];

    float acc[8];
    #pragma unroll
    for (int j = 0; j < 8; j++) acc[j] = 0.0f;

    #pragma unroll 2
    for (int e0 = off; e0 < end; e0 += 2) {
        int e = e0 + hf;
        if (e < end) {
            int2 ed = g_edge[e];
            float c = __int_as_float(ed.y);
            uint4 v = src[(size_t)ed.x * 16 + li];
            __half2* hp = (__half2*)&v;
            float2 f0 = __half22float2(hp[0]);
            float2 f1 = __half22float2(hp[1]);
            float2 f2 = __half22float2(hp[2]);
            float2 f3 = __half22float2(hp[3]);
            acc[0] += c * f0.x; acc[1] += c * f0.y;
            acc[2] += c * f1.x; acc[3] += c * f1.y;
            acc[4] += c * f2.x; acc[5] += c * f2.y;
            acc[6] += c * f3.x; acc[7] += c * f3.y;
        }
    }
    #pragma unroll
    for (int j = 0; j < 8; j++)
        acc[j] += __shfl_xor_sync(0xffffffffu, acc[j], 16);

    float di = g_dinv[node];
    float d2 = di * di;
    uint4 sv = src[(size_t)node * 16 + li];
    __half2* sh = (__half2*)&sv;
    float2 s0 = __half22float2(sh[2 * hf + 0]);
    float2 s1 = __half22float2(sh[2 * hf + 1]);
    float4 b4 = ((const float4*)bias)[li * 2 + hf];

    float4 r;
    r.x = di * acc[4 * hf + 0] + d2 * s0.x + b4.x;
    r.y = di * acc[4 * hf + 1] + d2 * s0.y + b4.y;
    r.z = di * acc[4 * hf + 2] + d2 * s1.x + b4.z;
    r.w = di * acc[4 * hf + 3] + d2 * s1.y + b4.w;
    if (do_relu) {
        r.x = fmaxf(r.x, 0.f); r.y = fmaxf(r.y, 0.f);
        r.z = fmaxf(r.z, 0.f); r.w = fmaxf(r.w, 0.f);
    }
    return r;
}

// ================ fused2: per block — agg1 (32 nodes -> smem) then gemm2 on them ================
__global__ __launch_bounds__(256) void fused2_kernel(const float* __restrict__ b1,
                                                     const float* __restrict__ W2, int n) {
    __shared__ float4 Xs[32 * DIM4];       // 32 post-relu x2 rows (16KB)
    __shared__ ulonglong2 Ws[32 * DIM4];   // W2 quarter (16KB)

    int lane = threadIdx.x & 31, wid = threadIdx.x >> 5;
    int hf = lane >> 4, li = lane & 15;
    int base = blockIdx.x * 32;

    // ---- phase A: aggregate layer-1 for nodes [base, base+32) into Xs ----
    #pragma unroll 1
    for (int j = 0; j < 4; j++) {
        int node = base + wid * 4 + j;
        if (node < n) {
            float4 r = agg_node(g_h16a, b1, node, hf, li, 1);
            Xs[(wid * 4 + j) * DIM4 + li * 2 + hf] = r;
        }
    }
    __syncthreads();

    // ---- phase B: gemm2 on the 32 smem rows -> g_h16b ----
    int r0 = wid * 4;  // local row
    unsigned long long a01[4], a23[4];
    #pragma unroll
    for (int ri = 0; ri < 4; ri++) { a01[ri] = 0ull; a23[ri] = 0ull; }

    #pragma unroll 1
    for (int q = 0; q < 4; q++) {
        const ulonglong2* Wq = (const ulonglong2*)(W2 + (size_t)q * 32 * DIM);
        for (int idx = threadIdx.x; idx < 32 * DIM4; idx += 256)
            Ws[idx] = Wq[idx];
        __syncthreads();
        if (base + r0 < n) {
            #pragma unroll
            for (int kk = 0; kk < 8; kk++) {
                ulonglong2 w0 = Ws[(4 * kk + 0) * DIM4 + lane];
                ulonglong2 w1 = Ws[(4 * kk + 1) * DIM4 + lane];
                ulonglong2 w2 = Ws[(4 * kk + 2) * DIM4 + lane];
                ulonglong2 w3 = Ws[(4 * kk + 3) * DIM4 + lane];
                #pragma unroll
                for (int ri = 0; ri < 4; ri++) {
                    if (base + r0 + ri < n) {
                        float4 xv = Xs[(r0 + ri) * DIM4 + q * 8 + kk];
                        unsigned long long x0 = dup2(xv.x), x1 = dup2(xv.y);
                        unsigned long long x2 = dup2(xv.z), x3 = dup2(xv.w);
                        a01[ri] = fma2(x0, w0.x, a01[ri]); a23[ri] = fma2(x0, w0.y, a23[ri]);
                        a01[ri] = fma2(x1, w1.x, a01[ri]); a23[ri] = fma2(x1, w1.y, a23[ri]);
                        a01[ri] = fma2(x2, w2.x, a01[ri]); a23[ri] = fma2(x2, w2.y, a23[ri]);
                        a01[ri] = fma2(x3, w3.x, a01[ri]); a23[ri] = fma2(x3, w3.y, a23[ri]);
                    }
                }
            }
        }
        __syncthreads();
    }

    uint2* H2 = (uint2*)g_h16b;
    #pragma unroll
    for (int ri = 0; ri < 4; ri++) {
        int r = base + r0 + ri;
        if (r < n) {
            float2 c01 = unpack2(a01[ri]);
            float2 c23 = unpack2(a23[ri]);
            __half2 p0 = __floats2half2_rn(c01.x, c01.y);
            __half2 p1 = __floats2half2_rn(c23.x, c23.y);
            uint2 o; o.x = *(unsigned*)&p0; o.y = *(unsigned*)&p1;
            H2[(size_t)r * 32 + lane] = o;
        }
    }
}

// ---------------- agg2: final aggregation from g_h16b -> out ----------------
__global__ __launch_bounds__(256) void agg2_kernel(const float* __restrict__ b2,
                                                   float* __restrict__ out, int n) {
    int gw = (blockIdx.x * blockDim.x + threadIdx.x) >> 5;
    int lane = threadIdx.x & 31;
    if (gw >= n) return;
    int hf = lane >> 4, li = lane & 15;
    float4 r = agg_node(g_h16b, b2, gw, hf, li, 0);
    ((float4*)out)[(size_t)gw * DIM4 + li * 2 + hf] = r;
}

// ---------------- launch (kernel launches ONLY — graph-capturable) ----------------
extern "C" void kernel_launch(void* const* d_in, const int* in_sizes, int n_in,
                              void* d_out, int out_size) {
    const float* x  = (const float*)d_in[0];
    const void*  ei = d_in[1];                 // [2, E], int32 OR int64
    const float* ew = (const float*)d_in[2];
    const float* W1 = (const float*)d_in[3];
    const float* b1 = (const float*)d_in[4];
    const float* W2 = (const float*)d_in[5];
    const float* b2 = (const float*)d_in[6];
    float* out = (float*)d_out;

    int n = in_sizes[0] / DIM;   // 100000
    int E = in_sizes[2];         // 3200000

    int nb_n    = (n + 255) / 256;
    int nb_e256 = (E + 255) / 256;
    int nb_e512 = (E + 511) / 512;
    int nb_wn   = (n * 32 + 255) / 256;   // one warp per node
    int nb_g    = (n + 31) / 32;
    int nb_s    = (n + 1023) / 1024;

    // init (+dtype detect), then gemm1 ∥ deg_hist fused by block range
    init_kernel<<<nb_n, 256>>>((const int*)ei, n);
    fused1_kernel<<<nb_g + nb_e256, 256>>>(x, W1, ei, ew, E, n, nb_g);

    // CSR offsets
    scan_phase1<<<nb_s, 256>>>(n);
    scan_phase2<<<1, 32>>>();
    scan_phase3<<<nb_s, 256>>>(n);
    scatter_kernel<<<nb_e512, 512>>>(ei, ew, E, n);

    // agg1 -> gemm2 fused per block (x2 never hits global memory)
    fused2_kernel<<<nb_g, 256>>>(b1, W2, n);

    // final aggregation
    agg2_kernel<<<nb_wn, 256>>>(b2, out, n);
}

// round 7
// speedup vs baseline: 1.0888x; 1.0888x over previous
#include <cuda_runtime.h>
#include <cuda_fp16.h>
#include <cuda_bf16.h>
#include <stdint.h>

#define N_NODES 100000
#define N_EDGES 3200000
#define DIM 128
#define DIM4 32
#define SCAN_NB 98   // ceil(100000/1024)

// ---------------- scratch (device globals) ----------------
__device__ int                g_is64;
__device__ int                g_done;
__device__ unsigned long long g_dh[N_NODES];   // [40,64) = count, [0,40) = deg in 2^-24 fixed pt
__device__ float              g_dinv[N_NODES];
__device__ int                g_hist[N_NODES];
__device__ int                g_offs[N_NODES];
__device__ int                g_cursor[N_NODES];
__device__ int2               g_edge[N_EDGES];  // (src row, coef bits)
__device__ int                g_psum[128];
__device__ int                g_poff[128];
__device__ uint4              g_h16[(size_t)N_NODES * 16];  // fp16 messages: 128 halfs/row
__device__ float              g_x2[(size_t)N_NODES * DIM];  // layer-1 output (fp32)

// ---------------- edge index readers (dtype-agnostic) ----------------
__device__ __forceinline__ int read_row(const void* ei, int E, int i) {
    if (g_is64) return (int)((const long long*)ei)[i];
    return ((const int*)ei)[i];
}
__device__ __forceinline__ int read_col(const void* ei, int E, int i) {
    if (g_is64) return (int)((const long long*)ei)[(size_t)E + i];
    return ((const int*)ei)[(size_t)E + i];
}

// ---------------- init: dh = self-loop (deg=1.0 fixed-pt, count 0); dtype detect ----------------
__global__ void init_kernel(const int* ei_words, int n) {
    int i = blockIdx.x * blockDim.x + threadIdx.x;
    if (i < n) g_dh[i] = (1ULL << 24);
    if (i == 0) {
        g_done = 0;
        int is64 = 1;
        #pragma unroll 1
        for (int k = 0; k < 64; k++)
            if (ei_words[2 * k + 1] != 0) { is64 = 0; break; }
        g_is64 = is64;
    }
}

// ---------------- deg+hist: ONE u64 reduction per edge ----------------
__global__ void deg_hist_kernel(const void* __restrict__ ei,
                                const float* __restrict__ ew, int E, int n) {
    int i = blockIdx.x * blockDim.x + threadIdx.x;
    if (i < E) {
        int c = read_col(ei, E, i);
        if ((unsigned)c >= (unsigned)n) return;
        unsigned long long fx = (unsigned long long)__float2uint_rn(ew[i] * 16777216.0f);
        atomicAdd(&g_dh[c], (1ULL << 40) | fx);   // no return use -> REDG
    }
}

// ---------------- scan phase 1+2 fused: partials, dinv, hist; last block scans partials ----------------
__global__ __launch_bounds__(256) void scan_phase12(int n, int nb) {
    __shared__ int ws[8];
    __shared__ int s_last;
    int b = blockIdx.x, tid = threadIdx.x;
    int base = b * 1024;
    int s = 0;
    #pragma unroll
    for (int j = 0; j < 4; j++) {
        int i = base + j * 256 + tid;
        if (i < n) {
            unsigned long long dh = g_dh[i];
            int cnt = (int)(dh >> 40);
            g_hist[i] = cnt;
            s += cnt;
            float d = (float)(dh & 0xFFFFFFFFFFULL) * (1.0f / 16777216.0f);
            g_dinv[i] = (d > 0.0f) ? rsqrtf(d) : 0.0f;
        }
    }
    #pragma unroll
    for (int o = 16; o; o >>= 1) s += __shfl_xor_sync(0xffffffffu, s, o);
    if ((tid & 31) == 0) ws[tid >> 5] = s;
    __syncthreads();
    if (tid == 0) {
        int t = 0;
        #pragma unroll
        for (int j = 0; j < 8; j++) t += ws[j];
        g_psum[b] = t;
        __threadfence();
        int ticket = atomicAdd(&g_done, 1);
        s_last = (ticket == nb - 1);
    }
    __syncthreads();
    // last-arriving block: warp 0 performs the cross-block exclusive scan
    if (s_last && tid < 32) {
        int lane = tid;
        int carry = 0;
        #pragma unroll
        for (int bb = 0; bb < SCAN_NB; bb += 32) {
            int i = bb + lane;
            int v = (i < SCAN_NB) ? ((volatile int*)g_psum)[i] : 0;
            int incl = v;
            #pragma unroll
            for (int st = 1; st < 32; st <<= 1) {
                int t = __shfl_up_sync(0xffffffffu, incl, st);
                if (lane >= st) incl += t;
            }
            if (i < SCAN_NB) g_poff[i] = carry + incl - v;
            carry += __shfl_sync(0xffffffffu, incl, 31);
        }
    }
}

// ---------------- scan phase 3: local exclusive scan + block offset ----------------
__global__ __launch_bounds__(256) void scan_phase3(int n) {
    __shared__ int wsum[8];
    int b = blockIdx.x, tid = threadIdx.x, lane = tid & 31, wid = tid >> 5;
    int base = b * 1024 + tid * 4;
    int v0 = 0, v1 = 0, v2 = 0, v3 = 0;
    if (base + 3 < n) {
        int4 v = *(const int4*)&g_hist[base];
        v0 = v.x; v1 = v.y; v2 = v.z; v3 = v.w;
    } else {
        if (base + 0 < n) v0 = g_hist[base + 0];
        if (base + 1 < n) v1 = g_hist[base + 1];
        if (base + 2 < n) v2 = g_hist[base + 2];
        if (base + 3 < n) v3 = g_hist[base + 3];
    }
    int t = v0 + v1 + v2 + v3;
    int incl = t;
    #pragma unroll
    for (int s = 1; s < 32; s <<= 1) {
        int u = __shfl_up_sync(0xffffffffu, incl, s);
        if (lane >= s) incl += u;
    }
    if (lane == 31) wsum[wid] = incl;
    __syncthreads();
    if (tid == 0) {
        int run = 0;
        #pragma unroll
        for (int j = 0; j < 8; j++) { int u = wsum[j]; wsum[j] = run; run += u; }
    }
    __syncthreads();
    int excl = g_poff[b] + wsum[wid] + incl - t;
    if (base + 0 < n) { g_offs[base + 0] = excl; g_cursor[base + 0] = excl; } excl += v0;
    if (base + 1 < n) { g_offs[base + 1] = excl; g_cursor[base + 1] = excl; } excl += v1;
    if (base + 2 < n) { g_offs[base + 2] = excl; g_cursor[base + 2] = excl; } excl += v2;
    if (base + 3 < n) { g_offs[base + 3] = excl; g_cursor[base + 3] = excl; }
}

// ---------------- scatter edges into CSR bins; single int2 store per edge ----------------
__global__ void scatter_kernel(const void* __restrict__ ei,
                               const float* __restrict__ ew, int E, int n) {
    int i = blockIdx.x * blockDim.x + threadIdx.x;
    if (i < E) {
        int r = read_row(ei, E, i);
        int c = read_col(ei, E, i);
        if ((unsigned)r >= (unsigned)n || (unsigned)c >= (unsigned)n) return;
        int pos = atomicAdd(&g_cursor[c], 1);
        if ((unsigned)pos < (unsigned)E)
            g_edge[pos] = make_int2(r, __float_as_int(ew[i] * g_dinv[r]));
    }
}

// ---------------- f32x2 helpers ----------------
__device__ __forceinline__ unsigned long long dup2(float v) {
    unsigned long long d;
    asm("mov.b64 %0, {%1, %1};" : "=l"(d) : "f"(v));
    return d;
}
__device__ __forceinline__ unsigned long long fma2(unsigned long long a,
                                                   unsigned long long b,
                                                   unsigned long long c) {
    unsigned long long d;
    asm("fma.rn.f32x2 %0, %1, %2, %3;" : "=l"(d) : "l"(a), "l"(b), "l"(c));
    return d;
}
__device__ __forceinline__ float2 unpack2(unsigned long long v) {
    float2 f;
    f.x = __uint_as_float((unsigned)(v & 0xffffffffull));
    f.y = __uint_as_float((unsigned)(v >> 32));
    return f;
}

// ---------------- GEMM: g_h16 = (x @ W) as fp16  (N x 128 @ 128 x 128) ----------------
// packed-pair FFMA2 math; W K-halves staged in 32KB static smem. (R5-proven)
__global__ __launch_bounds__(256) void gemm_kernel(const float* __restrict__ x_ext,
                                                   const float* __restrict__ W,
                                                   int use_x2, int n) {
    __shared__ ulonglong2 Ws[64 * DIM4];  // 64 k-rows x 128 cols = 32KB

    const float* x = use_x2 ? (const float*)g_x2 : x_ext;
    const float4* X4 = (const float4*)x;

    int lane = threadIdx.x & 31, wid = threadIdx.x >> 5;
    int r0 = blockIdx.x * 32 + wid * 4;

    unsigned long long a01[4], a23[4];
    #pragma unroll
    for (int ri = 0; ri < 4; ri++) { a01[ri] = 0ull; a23[ri] = 0ull; }

    #pragma unroll
    for (int half = 0; half < 2; half++) {
        const ulonglong2* Wh = (const ulonglong2*)(W + (size_t)half * 64 * DIM);
        for (int idx = threadIdx.x; idx < 64 * DIM4; idx += 256)
            Ws[idx] = Wh[idx];
        __syncthreads();

        if (r0 < n) {
            #pragma unroll 4
            for (int kk = 0; kk < 16; kk++) {
                ulonglong2 w0 = Ws[(4 * kk + 0) * DIM4 + lane];
                ulonglong2 w1 = Ws[(4 * kk + 1) * DIM4 + lane];
                ulonglong2 w2 = Ws[(4 * kk + 2) * DIM4 + lane];
                ulonglong2 w3 = Ws[(4 * kk + 3) * DIM4 + lane];
                #pragma unroll
                for (int ri = 0; ri < 4; ri++) {
                    int r = r0 + ri;
                    if (r < n) {
                        float4 xv = X4[(size_t)r * DIM4 + half * 16 + kk];
                        unsigned long long x0 = dup2(xv.x), x1 = dup2(xv.y);
                        unsigned long long x2 = dup2(xv.z), x3 = dup2(xv.w);
                        a01[ri] = fma2(x0, w0.x, a01[ri]); a23[ri] = fma2(x0, w0.y, a23[ri]);
                        a01[ri] = fma2(x1, w1.x, a01[ri]); a23[ri] = fma2(x1, w1.y, a23[ri]);
                        a01[ri] = fma2(x2, w2.x, a01[ri]); a23[ri] = fma2(x2, w2.y, a23[ri]);
                        a01[ri] = fma2(x3, w3.x, a01[ri]); a23[ri] = fma2(x3, w3.y, a23[ri]);
                    }
                }
            }
        }
        __syncthreads();
    }

    uint2* H2 = (uint2*)g_h16;  // row = 32 x uint2 (256B of fp16)
    #pragma unroll
    for (int ri = 0; ri < 4; ri++) {
        int r = r0 + ri;
        if (r < n) {
            float2 c01 = unpack2(a01[ri]);
            float2 c23 = unpack2(a23[ri]);
            __half2 p0 = __floats2half2_rn(c01.x, c01.y);
            __half2 p1 = __floats2half2_rn(c23.x, c23.y);
            uint2 o;
            o.x = *(unsigned*)&p0;
            o.y = *(unsigned*)&p1;
            H2[(size_t)r * 32 + lane] = o;
        }
    }
}

// ---------------- pull aggregation (fp16 gather): one warp per node, 2 edges/iter ----------------
__global__ __launch_bounds__(256) void agg_kernel(const float* __restrict__ bias,
                                                  float* __restrict__ out_ext,
                                                  int n, int do_relu, int dst_is_x2) {
    int gw = (blockIdx.x * blockDim.x + threadIdx.x) >> 5;
    int lane = threadIdx.x & 31;
    if (gw >= n) return;
    int i = gw;
    int half = lane >> 4;    // which of 2 concurrent edges
    int li = lane & 15;      // 16B chunk within the 256B fp16 row

    int off = g_offs[i];
    int end = off + g_hist[i];

    float acc[8];
    #pragma unroll
    for (int j = 0; j < 8; j++) acc[j] = 0.0f;

    #pragma unroll 2
    for (int e0 = off; e0 < end; e0 += 2) {
        int e = e0 + half;
        if (e < end) {
            int2 ed = g_edge[e];
            float c = __int_as_float(ed.y);
            uint4 v = g_h16[(size_t)ed.x * 16 + li];
            __half2* hp = (__half2*)&v;
            float2 f0 = __half22float2(hp[0]);
            float2 f1 = __half22float2(hp[1]);
            float2 f2 = __half22float2(hp[2]);
            float2 f3 = __half22float2(hp[3]);
            acc[0] += c * f0.x; acc[1] += c * f0.y;
            acc[2] += c * f1.x; acc[3] += c * f1.y;
            acc[4] += c * f2.x; acc[5] += c * f2.y;
            acc[6] += c * f3.x; acc[7] += c * f3.y;
        }
    }
    #pragma unroll
    for (int j = 0; j < 8; j++)
        acc[j] += __shfl_xor_sync(0xffffffffu, acc[j], 16);

    float di = g_dinv[i];
    float d2 = di * di;
    uint4 sv = g_h16[(size_t)i * 16 + li];
    __half2* sh = (__half2*)&sv;
    float2 s0 = __half22float2(sh[2 * half + 0]);
    float2 s1 = __half22float2(sh[2 * half + 1]);
    float4 b4 = ((const float4*)bias)[li * 2 + half];

    float4 r;
    r.x = di * acc[4 * half + 0] + d2 * s0.x + b4.x;
    r.y = di * acc[4 * half + 1] + d2 * s0.y + b4.y;
    r.z = di * acc[4 * half + 2] + d2 * s1.x + b4.z;
    r.w = di * acc[4 * half + 3] + d2 * s1.y + b4.w;
    if (do_relu) {
        r.x = fmaxf(r.x, 0.f); r.y = fmaxf(r.y, 0.f);
        r.z = fmaxf(r.z, 0.f); r.w = fmaxf(r.w, 0.f);
    }
    float4* dst = dst_is_x2 ? (float4*)g_x2 : (float4*)out_ext;
    dst[(size_t)i * 32 + li * 2 + half] = r;
}

// ---------------- launch (kernel launches ONLY — graph-capturable) ----------------
extern "C" void kernel_launch(void* const* d_in, const int* in_sizes, int n_in,
                              void* d_out, int out_size) {
    const float* x  = (const float*)d_in[0];
    const void*  ei = d_in[1];                 // [2, E], int32 OR int64
    const float* ew = (const float*)d_in[2];
    const float* W1 = (const float*)d_in[3];
    const float* b1 = (const float*)d_in[4];
    const float* W2 = (const float*)d_in[5];
    const float* b2 = (const float*)d_in[6];
    float* out = (float*)d_out;

    int n = in_sizes[0] / DIM;   // 100000
    int E = in_sizes[2];         // 3200000

    int nb_n  = (n + 255) / 256;
    int nb_e  = (E + 511) / 512;
    int nb_wn = (n * 32 + 255) / 256;  // one warp per node
    int nb_g  = (n + 31) / 32;
    int nb_s  = (n + 1023) / 1024;

    // preprocessing: CSR-ize edges by destination
    init_kernel<<<nb_n, 256>>>((const int*)ei, n);
    deg_hist_kernel<<<nb_e, 512>>>(ei, ew, E, n);
    scan_phase12<<<nb_s, 256>>>(n, nb_s);
    scan_phase3<<<nb_s, 256>>>(n);
    scatter_kernel<<<nb_e, 512>>>(ei, ew, E, n);

    // layer 1: g_h16 = fp16(x @ W1) ; g_x2 = agg + b1, relu
    gemm_kernel<<<nb_g, 256>>>(x, W1, /*use_x2=*/0, n);
    agg_kernel<<<nb_wn, 256>>>(b1, out, n, /*relu=*/1, /*dst_is_x2=*/1);

    // layer 2: g_h16 = fp16(g_x2 @ W2) ; out = agg + b2
    gemm_kernel<<<nb_g, 256>>>(x, W2, /*use_x2=*/1, n);
    agg_kernel<<<nb_wn, 256>>>(b2, out, n, /*relu=*/0, /*dst_is_x2=*/0);
}